// round 1
// baseline (speedup 1.0000x reference)
#include <cuda_runtime.h>
#include <cstdint>
#include <cstddef>

// Problem constants: out[M,N] = x[M,K] @ (w[K,N] + 2 * lora_a[K,16] @ lora_b[16,N])
#define M_DIM 8192
#define N_DIM 8192
#define K_DIM 2048

// 64 MB scratch for the fused weight (device global: allocation-free per harness rules)
__device__ float g_wf[(size_t)K_DIM * N_DIM];

// ---------------------------------------------------------------------------
// Kernel 1: W' = w + 2 * A @ B   (rank-16, memory-bound, ~25 us)
// ---------------------------------------------------------------------------
__global__ __launch_bounds__(256) void fuse_weights(const float* __restrict__ w,
                                                    const float* __restrict__ la,
                                                    const float* __restrict__ lb) {
    const int f = blockIdx.x * 256 + threadIdx.x;   // 0..8191
    const int d0 = blockIdx.y * 32;                 // 64 blocks of 32 rows
    float b[16];
#pragma unroll
    for (int r = 0; r < 16; r++) b[r] = lb[r * N_DIM + f];
#pragma unroll 4
    for (int d = d0; d < d0 + 32; d++) {
        const float4* a4 = reinterpret_cast<const float4*>(la + d * 16);
        float acc = 0.f;
#pragma unroll
        for (int q = 0; q < 4; q++) {
            float4 a = a4[q];
            acc += a.x * b[q * 4 + 0] + a.y * b[q * 4 + 1] +
                   a.z * b[q * 4 + 2] + a.w * b[q * 4 + 3];
        }
        const size_t off = (size_t)d * N_DIM + f;
        g_wf[off] = w[off] + 2.0f * acc;
    }
}

// ---------------------------------------------------------------------------
// Kernel 2: tf32 mma.sync GEMM, 128x128x32 CTA tile, cp.async double buffer
// ---------------------------------------------------------------------------
__device__ __forceinline__ uint32_t f2tf32(float x) {
    uint32_t u;
    asm("cvt.rna.tf32.f32 %0, %1;" : "=r"(u) : "f"(x));
    return u;
}

__device__ __forceinline__ void mma8(float c[4], const uint32_t a[4], const uint32_t b[2]) {
    asm volatile(
        "mma.sync.aligned.m16n8k8.row.col.f32.tf32.tf32.f32 "
        "{%0,%1,%2,%3}, {%4,%5,%6,%7}, {%8,%9}, {%0,%1,%2,%3};\n"
        : "+f"(c[0]), "+f"(c[1]), "+f"(c[2]), "+f"(c[3])
        : "r"(a[0]), "r"(a[1]), "r"(a[2]), "r"(a[3]), "r"(b[0]), "r"(b[1]));
}

constexpr int AS_STRIDE = 36;             // 32 + 4 pad (A frag banks: 4*grp+tig, conflict-free)
constexpr int BS_STRIDE = 136;            // 128 + 8 pad (B frag banks: 8*tig+grp, conflict-free)
constexpr int A_STAGE = 128 * AS_STRIDE;  // 4608 floats
constexpr int B_STAGE = 32 * BS_STRIDE;   // 4352 floats
constexpr int SMEM_FLOATS = 2 * (A_STAGE + B_STAGE);  // 17920 floats = 71680 B

__global__ __launch_bounds__(256, 2) void gemm_tf32(const float* __restrict__ A,
                                                    float* __restrict__ C) {
    extern __shared__ float smem[];
    const int tid = threadIdx.x;
    const int lane = tid & 31;
    const int warp = tid >> 5;
    const int wm = warp & 1;   // 2 warps along M (64 rows each)
    const int wn = warp >> 1;  // 4 warps along N (32 cols each)
    const int grp = lane >> 2; // 0..7
    const int tig = lane & 3;  // 0..3
    const int blockM = blockIdx.y * 128;
    const int blockN = blockIdx.x * 128;

    const uint32_t smem_u = (uint32_t)__cvta_generic_to_shared(smem);

    float acc[4][4][4];
#pragma unroll
    for (int i = 0; i < 4; i++)
#pragma unroll
        for (int j = 0; j < 4; j++)
#pragma unroll
            for (int l = 0; l < 4; l++) acc[i][j][l] = 0.f;

    auto load_stage = [&](int s, int k0) {
        const uint32_t aBase = smem_u + (uint32_t)(s * A_STAGE) * 4u;
        const uint32_t bBase = smem_u + (uint32_t)(2 * A_STAGE + s * B_STAGE) * 4u;
        // A tile: 128 rows x 32 cols = 1024 float4, 4 per thread
#pragma unroll
        for (int i = 0; i < 4; i++) {
            const int idx = tid + i * 256;
            const int row = idx >> 3, cc = idx & 7;
            const float* g = A + (size_t)(blockM + row) * K_DIM + k0 + cc * 4;
            const uint32_t d = aBase + (uint32_t)(row * AS_STRIDE + cc * 4) * 4u;
            asm volatile("cp.async.cg.shared.global [%0], [%1], 16;\n" ::"r"(d), "l"(g));
        }
        // B tile: 32 rows x 128 cols = 1024 float4, 4 per thread
#pragma unroll
        for (int i = 0; i < 4; i++) {
            const int idx = tid + i * 256;
            const int row = idx >> 5, cc = idx & 31;
            const float* g = g_wf + (size_t)(k0 + row) * N_DIM + blockN + cc * 4;
            const uint32_t d = bBase + (uint32_t)(row * BS_STRIDE + cc * 4) * 4u;
            asm volatile("cp.async.cg.shared.global [%0], [%1], 16;\n" ::"r"(d), "l"(g));
        }
    };

    load_stage(0, 0);
    asm volatile("cp.async.commit_group;\n" ::: "memory");

    const int KTILES = K_DIM / 32;  // 64
    for (int kt = 0; kt < KTILES; kt++) {
        asm volatile("cp.async.wait_group 0;\n" ::: "memory");
        __syncthreads();
        if (kt + 1 < KTILES) load_stage((kt + 1) & 1, (kt + 1) * 32);
        asm volatile("cp.async.commit_group;\n" ::: "memory");

        const float* As = smem + (kt & 1) * A_STAGE;
        const float* Bs = smem + 2 * A_STAGE + (kt & 1) * B_STAGE;
#pragma unroll
        for (int ks = 0; ks < 4; ks++) {
            const int kk = ks * 8;
            uint32_t af[4][4], bf[4][2];
#pragma unroll
            for (int mi = 0; mi < 4; mi++) {
                const float* ap = As + (wm * 64 + mi * 16 + grp) * AS_STRIDE + kk + tig;
                af[mi][0] = f2tf32(ap[0]);
                af[mi][1] = f2tf32(ap[8 * AS_STRIDE]);
                af[mi][2] = f2tf32(ap[4]);
                af[mi][3] = f2tf32(ap[8 * AS_STRIDE + 4]);
            }
#pragma unroll
            for (int ni = 0; ni < 4; ni++) {
                const float* bp = Bs + (kk + tig) * BS_STRIDE + wn * 32 + ni * 8 + grp;
                bf[ni][0] = f2tf32(bp[0]);
                bf[ni][1] = f2tf32(bp[4 * BS_STRIDE]);
            }
#pragma unroll
            for (int mi = 0; mi < 4; mi++)
#pragma unroll
                for (int ni = 0; ni < 4; ni++)
                    mma8(acc[mi][ni], af[mi], bf[ni]);
        }
        // no trailing syncthreads needed: next iteration's wait+sync orders
        // compute(kt) before any thread overwrites buffer (kt)&1 at kt+2.
    }

    // Epilogue: c0/c1 at (row, 2*tig[+1]), c2/c3 at (row+8, ...); float2 stores
#pragma unroll
    for (int mi = 0; mi < 4; mi++) {
        const int r0 = blockM + wm * 64 + mi * 16 + grp;
#pragma unroll
        for (int ni = 0; ni < 4; ni++) {
            const int c0 = blockN + wn * 32 + ni * 8 + 2 * tig;
            float2 v0 = make_float2(acc[mi][ni][0], acc[mi][ni][1]);
            float2 v1 = make_float2(acc[mi][ni][2], acc[mi][ni][3]);
            *reinterpret_cast<float2*>(C + (size_t)r0 * N_DIM + c0) = v0;
            *reinterpret_cast<float2*>(C + (size_t)(r0 + 8) * N_DIM + c0) = v1;
        }
    }
}

// ---------------------------------------------------------------------------
extern "C" void kernel_launch(void* const* d_in, const int* in_sizes, int n_in,
                              void* d_out, int out_size) {
    const float* x = (const float*)d_in[0];   // [4,2048,2048]
    const float* w = (const float*)d_in[1];   // [2048,8192]
    const float* la = (const float*)d_in[2];  // [2048,16]
    const float* lb = (const float*)d_in[3];  // [16,8192]
    float* out = (float*)d_out;               // [4,2048,8192] fp32

    fuse_weights<<<dim3(N_DIM / 256, K_DIM / 32), 256>>>(w, la, lb);

    const int smem_bytes = SMEM_FLOATS * 4;  // 71680
    cudaFuncSetAttribute(gemm_tf32, cudaFuncAttributeMaxDynamicSharedMemorySize, smem_bytes);
    gemm_tf32<<<dim3(N_DIM / 128, M_DIM / 128), 256, smem_bytes>>>(x, out);
}

// round 3
// speedup vs baseline: 1.1555x; 1.1555x over previous
#include <cuda_runtime.h>
#include <cstdint>
#include <cstddef>

// out[M,N] = x[M,K] @ (w[K,N] + 2 * lora_a[K,16] @ lora_b[16,N])
#define M_DIM 8192
#define N_DIM 8192
#define K_DIM 2048
#define SCALE 2.0f

// Scratch (device globals — allocation-free per harness rules).
// g_xr: x, rna-rounded to tf32 bits, k-permuted within 8-groups, [M,K]
// g_wt: fused W' = w + 2*A@B, rounded, TRANSPOSED [N,K], k-permuted
__device__ __align__(16) float g_xr[(size_t)M_DIM * K_DIM];
__device__ __align__(16) float g_wt[(size_t)N_DIM * K_DIM];

__device__ __forceinline__ float rna_tf32(float x) {
    uint32_t u; asm("cvt.rna.tf32.f32 %0, %1;" : "=r"(u) : "f"(x));
    return __uint_as_float(u);
}

// k-permutation within each 8-group: logical c -> 8*(c/8) + 2*(c&3) + ((c>>2)&1)
// (makes logical pairs (c, c+4) physically adjacent; applied to BOTH operands,
// so the GEMM result is unchanged)

// ---------------------------------------------------------------------------
// Kernel 1: x -> rounded + k-permuted. Each thread handles one 8-group.
// phys {0..3} = {l0,l4,l1,l5},  phys {4..7} = {l2,l6,l3,l7}
// ---------------------------------------------------------------------------
__global__ __launch_bounds__(256) void prep_x(const float4* __restrict__ x,
                                              float4* __restrict__ xr) {
    size_t i = ((size_t)blockIdx.x * 256 + threadIdx.x) * 2;
    float4 v0 = x[i], v1 = x[i + 1];
    float4 o0, o1;
    o0.x = rna_tf32(v0.x); o0.y = rna_tf32(v1.x);
    o0.z = rna_tf32(v0.y); o0.w = rna_tf32(v1.y);
    o1.x = rna_tf32(v0.z); o1.y = rna_tf32(v1.z);
    o1.z = rna_tf32(v0.w); o1.w = rna_tf32(v1.w);
    xr[i] = o0; xr[i + 1] = o1;
}

// ---------------------------------------------------------------------------
// Kernel 2: g_wt[n][P(k)] = rna(w[k][n] + 2*(A@B)[k][n]); 32x32 smem transpose
// ---------------------------------------------------------------------------
__global__ __launch_bounds__(256) void fuse_w_t(const float* __restrict__ w,
                                                const float* __restrict__ la,
                                                const float* __restrict__ lb) {
    __shared__ float t[32][33];
    __shared__ float bs[16][32];
    const int n0 = blockIdx.x * 32, k0 = blockIdx.y * 32;
    const int tid = threadIdx.x;
    const int tx = tid & 31, ty = tid >> 5;
    {
        int i0 = tid;
        bs[i0 >> 5][i0 & 31] = lb[(size_t)(i0 >> 5) * N_DIM + n0 + (i0 & 31)];
        int i1 = tid + 256;
        bs[i1 >> 5][i1 & 31] = lb[(size_t)(i1 >> 5) * N_DIM + n0 + (i1 & 31)];
    }
    __syncthreads();
#pragma unroll
    for (int i = 0; i < 4; i++) {
        const int kl = ty + 8 * i;
        const int k = k0 + kl;
        const float* ar = la + (size_t)k * 16;
        float acc = 0.f;
#pragma unroll
        for (int r = 0; r < 16; r++) acc += ar[r] * bs[r][tx];
        t[kl][tx] = rna_tf32(w[(size_t)k * N_DIM + n0 + tx] + SCALE * acc);
    }
    __syncthreads();
    const int ptx_ = (tx & 24) + 2 * (tx & 3) + ((tx >> 2) & 1);  // P(tx)
#pragma unroll
    for (int i = 0; i < 4; i++) {
        const int nl = ty + 8 * i;
        g_wt[(size_t)(n0 + nl) * K_DIM + k0 + ptx_] = t[tx][nl];
    }
}

// ---------------------------------------------------------------------------
// Kernel 3: tf32 mma.sync GEMM. CTA 128x128, warp 64x32, Ktile 32,
//           double-buffered cp.async. Both smem tiles [row][k], stride 40.
//           Fragment loads are conflict-free LDS.64 (k pre-permuted).
// ---------------------------------------------------------------------------
constexpr int STRIDE = 40;                 // 32 + 8 pad (floats)
constexpr int T_ST = 128 * STRIDE;         // one tile: 5120 floats (20 KB)
constexpr int STAGE = 2 * T_ST;            // A + B per stage (40 KB)
constexpr int SMEM_BYTES = 2 * STAGE * 4;  // 81920

__device__ __forceinline__ void lds64(uint32_t& a, uint32_t& b, uint32_t addr) {
    asm volatile("ld.shared.v2.b32 {%0,%1}, [%2];" : "=r"(a), "=r"(b) : "r"(addr));
}
__device__ __forceinline__ void mma8(float c[4], const uint32_t a[4], const uint32_t b[2]) {
    asm volatile(
        "mma.sync.aligned.m16n8k8.row.col.f32.tf32.tf32.f32 "
        "{%0,%1,%2,%3}, {%4,%5,%6,%7}, {%8,%9}, {%0,%1,%2,%3};\n"
        : "+f"(c[0]), "+f"(c[1]), "+f"(c[2]), "+f"(c[3])
        : "r"(a[0]), "r"(a[1]), "r"(a[2]), "r"(a[3]), "r"(b[0]), "r"(b[1]));
}

__global__ __launch_bounds__(256, 2) void gemm_tf32(const float* __restrict__ A,
                                                    const float* __restrict__ B,
                                                    float* __restrict__ C) {
    extern __shared__ float smem[];
    const int tid = threadIdx.x;
    const int lane = tid & 31;
    const int warp = tid >> 5;
    const int wm = warp & 1;   // 2 warps along M (64 rows)
    const int wn = warp >> 1;  // 4 warps along N (32 cols)
    const int grp = lane >> 2; // 0..7
    const int tig = lane & 3;  // 0..3
    const int blockM = blockIdx.y * 128;
    const int blockN = blockIdx.x * 128;

    const uint32_t smem_u = (uint32_t)__cvta_generic_to_shared(smem);

    float acc[4][4][4];
#pragma unroll
    for (int i = 0; i < 4; i++)
#pragma unroll
        for (int j = 0; j < 4; j++)
#pragma unroll
            for (int l = 0; l < 4; l++) acc[i][j][l] = 0.f;

    // cp.async loaders: each tile = 128 rows x 8 chunks of 16B -> 1024 per tile
    auto load_stage = [&](int s, int k0) {
        const uint32_t base = smem_u + (uint32_t)(s * STAGE) * 4u;
#pragma unroll
        for (int i = 0; i < 4; i++) {
            const int idx = tid + i * 256;
            const int row = idx >> 3, ch = idx & 7;
            const float* g = A + (size_t)(blockM + row) * K_DIM + k0 + ch * 4;
            const uint32_t d = base + (uint32_t)(row * STRIDE + ch * 4) * 4u;
            asm volatile("cp.async.cg.shared.global [%0], [%1], 16;\n" ::"r"(d), "l"(g));
        }
#pragma unroll
        for (int i = 0; i < 4; i++) {
            const int idx = tid + i * 256;
            const int row = idx >> 3, ch = idx & 7;
            const float* g = B + (size_t)(blockN + row) * K_DIM + k0 + ch * 4;
            const uint32_t d = base + (uint32_t)(T_ST + row * STRIDE + ch * 4) * 4u;
            asm volatile("cp.async.cg.shared.global [%0], [%1], 16;\n" ::"r"(d), "l"(g));
        }
    };

    load_stage(0, 0);
    asm volatile("cp.async.commit_group;\n" ::: "memory");

    const int KTILES = K_DIM / 32;  // 64
    for (int kt = 0; kt < KTILES; kt++) {
        asm volatile("cp.async.wait_group 0;\n" ::: "memory");
        __syncthreads();
        if (kt + 1 < KTILES) load_stage((kt + 1) & 1, (kt + 1) * 32);
        asm volatile("cp.async.commit_group;\n" ::: "memory");

        const uint32_t aB = smem_u + (uint32_t)((kt & 1) * STAGE) * 4u;
        const uint32_t bB = aB + (uint32_t)T_ST * 4u;
        // per-thread bases (bytes)
        const uint32_t aTh = aB + (uint32_t)((wm * 64 + grp) * STRIDE + 2 * tig) * 4u;
        const uint32_t bTh = bB + (uint32_t)((wn * 32 + grp) * STRIDE + 2 * tig) * 4u;
#pragma unroll
        for (int ks = 0; ks < 4; ks++) {
            const uint32_t ko = (uint32_t)(ks * 8) * 4u;
            uint32_t af[4][4], bf[4][2];
#pragma unroll
            for (int mi = 0; mi < 4; mi++) {
                const uint32_t ap = aTh + (uint32_t)(mi * 16 * STRIDE) * 4u + ko;
                lds64(af[mi][0], af[mi][2], ap);                              // rows grp
                lds64(af[mi][1], af[mi][3], ap + (uint32_t)(8 * STRIDE) * 4u); // rows grp+8
            }
#pragma unroll
            for (int ni = 0; ni < 4; ni++) {
                const uint32_t bp = bTh + (uint32_t)(ni * 8 * STRIDE) * 4u + ko;
                lds64(bf[ni][0], bf[ni][1], bp);
            }
#pragma unroll
            for (int mi = 0; mi < 4; mi++)
#pragma unroll
                for (int ni = 0; ni < 4; ni++)
                    mma8(acc[mi][ni], af[mi], bf[ni]);
        }
    }

    // Epilogue: c0/c1 at (row, 2*tig[+1]); c2/c3 at (row+8, ...)
#pragma unroll
    for (int mi = 0; mi < 4; mi++) {
        const int r0 = blockM + wm * 64 + mi * 16 + grp;
#pragma unroll
        for (int ni = 0; ni < 4; ni++) {
            const int c0 = blockN + wn * 32 + ni * 8 + 2 * tig;
            float2 v0 = make_float2(acc[mi][ni][0], acc[mi][ni][1]);
            float2 v1 = make_float2(acc[mi][ni][2], acc[mi][ni][3]);
            *reinterpret_cast<float2*>(C + (size_t)r0 * N_DIM + c0) = v0;
            *reinterpret_cast<float2*>(C + (size_t)(r0 + 8) * N_DIM + c0) = v1;
        }
    }
}

// ---------------------------------------------------------------------------
extern "C" void kernel_launch(void* const* d_in, const int* in_sizes, int n_in,
                              void* d_out, int out_size) {
    const float* x  = (const float*)d_in[0];  // [8192,2048]
    const float* w  = (const float*)d_in[1];  // [2048,8192]
    const float* la = (const float*)d_in[2];  // [2048,16]
    const float* lb = (const float*)d_in[3];  // [16,8192]
    float* out = (float*)d_out;               // [8192,8192]

    void *xr_p = nullptr, *wt_p = nullptr;
    cudaGetSymbolAddress(&xr_p, g_xr);
    cudaGetSymbolAddress(&wt_p, g_wt);

    prep_x<<<(int)(((size_t)M_DIM * K_DIM / 8) / 256), 256>>>(
        (const float4*)x, (float4*)xr_p);
    fuse_w_t<<<dim3(N_DIM / 32, K_DIM / 32), 256>>>(w, la, lb);

    cudaFuncSetAttribute(gemm_tf32, cudaFuncAttributeMaxDynamicSharedMemorySize, SMEM_BYTES);
    gemm_tf32<<<dim3(N_DIM / 128, M_DIM / 128), 256, SMEM_BYTES>>>(
        (const float*)xr_p, (const float*)wt_p, out);
}

// round 4
// speedup vs baseline: 1.1901x; 1.0300x over previous
#include <cuda_runtime.h>
#include <cstdint>
#include <cstddef>

// out[M,N] = x[M,K] @ (w[K,N] + 2 * lora_a[K,16] @ lora_b[16,N])
#define M_DIM 8192
#define N_DIM 8192
#define K_DIM 2048
#define SCALE 2.0f

// Scratch (device globals — allocation-free per harness rules).
// g_xr: x, rna-rounded to tf32 bits, k-permuted within 8-groups, [M,K]
// g_wt: fused W' = w + 2*A@B, rounded, TRANSPOSED [N,K], k-permuted
__device__ __align__(16) float g_xr[(size_t)M_DIM * K_DIM];
__device__ __align__(16) float g_wt[(size_t)N_DIM * K_DIM];

__device__ __forceinline__ float rna_tf32(float x) {
    uint32_t u; asm("cvt.rna.tf32.f32 %0, %1;" : "=r"(u) : "f"(x));
    return __uint_as_float(u);
}

// k-permutation within each 8-group: logical c -> 8*(c/8) + 2*(c&3) + ((c>>2)&1)
// (logical pairs (c, c+4) physically adjacent; applied to BOTH operands, so
// dot products — and the GEMM — are unchanged)

// ---------------------------------------------------------------------------
// Kernel 1: x -> rounded + k-permuted. Each thread handles one 8-group.
// ---------------------------------------------------------------------------
__global__ __launch_bounds__(256) void prep_x(const float4* __restrict__ x,
                                              float4* __restrict__ xr) {
    size_t i = ((size_t)blockIdx.x * 256 + threadIdx.x) * 2;
    float4 v0 = x[i], v1 = x[i + 1];
    float4 o0, o1;
    o0.x = rna_tf32(v0.x); o0.y = rna_tf32(v1.x);
    o0.z = rna_tf32(v0.y); o0.w = rna_tf32(v1.y);
    o1.x = rna_tf32(v0.z); o1.y = rna_tf32(v1.z);
    o1.z = rna_tf32(v0.w); o1.w = rna_tf32(v1.w);
    xr[i] = o0; xr[i + 1] = o1;
}

// ---------------------------------------------------------------------------
// Kernel 2: g_wt[n][P(k)] = rna(w[k][n] + 2*(A@B)[k][n]); 32x32 smem transpose
// ---------------------------------------------------------------------------
__global__ __launch_bounds__(256) void fuse_w_t(const float* __restrict__ w,
                                                const float* __restrict__ la,
                                                const float* __restrict__ lb) {
    __shared__ float t[32][33];
    __shared__ float bs[16][32];
    const int n0 = blockIdx.x * 32, k0 = blockIdx.y * 32;
    const int tid = threadIdx.x;
    const int tx = tid & 31, ty = tid >> 5;
    {
        int i0 = tid;
        bs[i0 >> 5][i0 & 31] = lb[(size_t)(i0 >> 5) * N_DIM + n0 + (i0 & 31)];
        int i1 = tid + 256;
        bs[i1 >> 5][i1 & 31] = lb[(size_t)(i1 >> 5) * N_DIM + n0 + (i1 & 31)];
    }
    __syncthreads();
#pragma unroll
    for (int i = 0; i < 4; i++) {
        const int kl = ty + 8 * i;
        const int k = k0 + kl;
        const float* ar = la + (size_t)k * 16;
        float acc = 0.f;
#pragma unroll
        for (int r = 0; r < 16; r++) acc += ar[r] * bs[r][tx];
        t[kl][tx] = rna_tf32(w[(size_t)k * N_DIM + n0 + tx] + SCALE * acc);
    }
    __syncthreads();
    const int ptx_ = (tx & 24) + 2 * (tx & 3) + ((tx >> 2) & 1);  // P(tx)
#pragma unroll
    for (int i = 0; i < 4; i++) {
        const int nl = ty + 8 * i;
        g_wt[(size_t)(n0 + nl) * K_DIM + k0 + ptx_] = t[tx][nl];
    }
}

// ---------------------------------------------------------------------------
// Kernel 3: tf32 mma.sync GEMM. CTA 128x128 / 128 threads, warp tile 64x64,
//           Ktile 32, double-buffered cp.async, conflict-free LDS.64 frags.
//           128 B smem per MMA -> tensor-pipe-bound (smem bw 2x headroom).
// ---------------------------------------------------------------------------
constexpr int STRIDE = 40;                 // 32 + 8 pad (floats)
constexpr int T_ST = 128 * STRIDE;         // one tile: 5120 floats (20 KB)
constexpr int STAGE = 2 * T_ST;            // A + B per stage (40 KB)
constexpr int SMEM_BYTES = 2 * STAGE * 4;  // 81920

__device__ __forceinline__ void lds64(uint32_t& a, uint32_t& b, uint32_t addr) {
    asm volatile("ld.shared.v2.b32 {%0,%1}, [%2];" : "=r"(a), "=r"(b) : "r"(addr));
}
__device__ __forceinline__ void mma8(float c[4], const uint32_t a[4], const uint32_t b[2]) {
    asm volatile(
        "mma.sync.aligned.m16n8k8.row.col.f32.tf32.tf32.f32 "
        "{%0,%1,%2,%3}, {%4,%5,%6,%7}, {%8,%9}, {%0,%1,%2,%3};\n"
        : "+f"(c[0]), "+f"(c[1]), "+f"(c[2]), "+f"(c[3])
        : "r"(a[0]), "r"(a[1]), "r"(a[2]), "r"(a[3]), "r"(b[0]), "r"(b[1]));
}

__global__ __launch_bounds__(128, 2) void gemm_tf32(const float* __restrict__ A,
                                                    const float* __restrict__ B,
                                                    float* __restrict__ C) {
    extern __shared__ float smem[];
    const int tid = threadIdx.x;
    const int lane = tid & 31;
    const int warp = tid >> 5;   // 0..3
    const int wm = warp >> 1;    // 2 warps along M (64 rows)
    const int wn = warp & 1;     // 2 warps along N (64 cols)
    const int grp = lane >> 2;   // 0..7
    const int tig = lane & 3;    // 0..3
    const int blockM = blockIdx.y * 128;
    const int blockN = blockIdx.x * 128;

    const uint32_t smem_u = (uint32_t)__cvta_generic_to_shared(smem);

    float acc[4][8][4];
#pragma unroll
    for (int i = 0; i < 4; i++)
#pragma unroll
        for (int j = 0; j < 8; j++)
#pragma unroll
            for (int l = 0; l < 4; l++) acc[i][j][l] = 0.f;

    // cp.async loaders: each tile = 128 rows x 8 chunks of 16B = 1024 float4
    auto load_stage = [&](int s, int k0) {
        const uint32_t base = smem_u + (uint32_t)(s * STAGE) * 4u;
#pragma unroll
        for (int i = 0; i < 8; i++) {
            const int idx = tid + i * 128;
            const int row = idx >> 3, ch = idx & 7;
            const float* g = A + (size_t)(blockM + row) * K_DIM + k0 + ch * 4;
            const uint32_t d = base + (uint32_t)(row * STRIDE + ch * 4) * 4u;
            asm volatile("cp.async.cg.shared.global [%0], [%1], 16;\n" ::"r"(d), "l"(g));
        }
#pragma unroll
        for (int i = 0; i < 8; i++) {
            const int idx = tid + i * 128;
            const int row = idx >> 3, ch = idx & 7;
            const float* g = B + (size_t)(blockN + row) * K_DIM + k0 + ch * 4;
            const uint32_t d = base + (uint32_t)(T_ST + row * STRIDE + ch * 4) * 4u;
            asm volatile("cp.async.cg.shared.global [%0], [%1], 16;\n" ::"r"(d), "l"(g));
        }
    };

    load_stage(0, 0);
    asm volatile("cp.async.commit_group;\n" ::: "memory");

    const int KTILES = K_DIM / 32;  // 64
    for (int kt = 0; kt < KTILES; kt++) {
        asm volatile("cp.async.wait_group 0;\n" ::: "memory");
        __syncthreads();
        if (kt + 1 < KTILES) load_stage((kt + 1) & 1, (kt + 1) * 32);
        asm volatile("cp.async.commit_group;\n" ::: "memory");

        const uint32_t aB = smem_u + (uint32_t)((kt & 1) * STAGE) * 4u;
        const uint32_t bB = aB + (uint32_t)T_ST * 4u;
        const uint32_t aTh = aB + (uint32_t)((wm * 64 + grp) * STRIDE + 2 * tig) * 4u;
        const uint32_t bTh = bB + (uint32_t)((wn * 64 + grp) * STRIDE + 2 * tig) * 4u;
#pragma unroll
        for (int ks = 0; ks < 4; ks++) {
            const uint32_t ko = (uint32_t)(ks * 8) * 4u;
            uint32_t af[4][4], bf[8][2];
#pragma unroll
            for (int mi = 0; mi < 4; mi++) {
                const uint32_t ap = aTh + (uint32_t)(mi * 16 * STRIDE) * 4u + ko;
                lds64(af[mi][0], af[mi][2], ap);                               // rows grp
                lds64(af[mi][1], af[mi][3], ap + (uint32_t)(8 * STRIDE) * 4u); // rows grp+8
            }
#pragma unroll
            for (int ni = 0; ni < 8; ni++) {
                const uint32_t bp = bTh + (uint32_t)(ni * 8 * STRIDE) * 4u + ko;
                lds64(bf[ni][0], bf[ni][1], bp);
            }
#pragma unroll
            for (int mi = 0; mi < 4; mi++)
#pragma unroll
                for (int ni = 0; ni < 8; ni++)
                    mma8(acc[mi][ni], af[mi], bf[ni]);
        }
    }

    // Epilogue: c0/c1 at (row, 2*tig[+1]); c2/c3 at (row+8, ...)
#pragma unroll
    for (int mi = 0; mi < 4; mi++) {
        const int r0 = blockM + wm * 64 + mi * 16 + grp;
#pragma unroll
        for (int ni = 0; ni < 8; ni++) {
            const int c0 = blockN + wn * 64 + ni * 8 + 2 * tig;
            float2 v0 = make_float2(acc[mi][ni][0], acc[mi][ni][1]);
            float2 v1 = make_float2(acc[mi][ni][2], acc[mi][ni][3]);
            *reinterpret_cast<float2*>(C + (size_t)r0 * N_DIM + c0) = v0;
            *reinterpret_cast<float2*>(C + (size_t)(r0 + 8) * N_DIM + c0) = v1;
        }
    }
}

// ---------------------------------------------------------------------------
extern "C" void kernel_launch(void* const* d_in, const int* in_sizes, int n_in,
                              void* d_out, int out_size) {
    const float* x  = (const float*)d_in[0];  // [8192,2048]
    const float* w  = (const float*)d_in[1];  // [2048,8192]
    const float* la = (const float*)d_in[2];  // [2048,16]
    const float* lb = (const float*)d_in[3];  // [16,8192]
    float* out = (float*)d_out;               // [8192,8192]

    void *xr_p = nullptr, *wt_p = nullptr;
    cudaGetSymbolAddress(&xr_p, g_xr);
    cudaGetSymbolAddress(&wt_p, g_wt);

    prep_x<<<(int)(((size_t)M_DIM * K_DIM / 8) / 256), 256>>>(
        (const float4*)x, (float4*)xr_p);
    fuse_w_t<<<dim3(N_DIM / 32, K_DIM / 32), 256>>>(w, la, lb);

    cudaFuncSetAttribute(gemm_tf32, cudaFuncAttributeMaxDynamicSharedMemorySize, SMEM_BYTES);
    gemm_tf32<<<dim3(N_DIM / 128, M_DIM / 128), 128, SMEM_BYTES>>>(
        (const float*)xr_p, (const float*)wt_p, out);
}